// round 1
// baseline (speedup 1.0000x reference)
#include <cuda_runtime.h>
#include <cuda_bf16.h>

// Problem constants
// x: [4, 2048, 1024] f32; Wq/Wk/Wv: [1024,1024] (out,in); bq/bk/bv: [1024]
// out: [4, 2048, 1024] f32
#define BATCH 4
#define SEQ   2048
#define DIM   1024   // INPUT_DIM == UNITS

// ---------------------------------------------------------------------------
// Scratch (device globals — allocation-free per harness rules)
// ---------------------------------------------------------------------------
__device__ float g_Q[(long)BATCH * SEQ * DIM];
__device__ float g_K[(long)BATCH * SEQ * DIM];
__device__ float g_V[(long)BATCH * SEQ * DIM];
__device__ float g_P[(long)BATCH * SEQ * SEQ];   // scores / probs (64 MB)

// ---------------------------------------------------------------------------
// Generic tiled SGEMM:
//   C[M,N] = alpha * A[M,K] (row-major, lda=K)  x  B  (+ bias[n])
//   TRANS_B = true : B is [N,K] row-major (ldb=K)  -> C = A * B^T
//   TRANS_B = false: B is [K,N] row-major (ldb=N)  -> C = A * B
// Batched over blockIdx.z via element strides.
// All dims assumed multiples of the tile (true for this problem).
// ---------------------------------------------------------------------------
#define BM 128
#define BN 128
#define BK 16

template <bool TRANS_B, bool HAS_BIAS>
__global__ __launch_bounds__(256, 2)
void gemm_kernel(const float* __restrict__ A,
                 const float* __restrict__ B,
                 const float* __restrict__ bias,
                 float* __restrict__ C,
                 int M, int N, int K,
                 long strideA, long strideB, long strideC,
                 float alpha)
{
    __shared__ float As[BK][BM + 4];
    __shared__ float Bs[BK][BN + 4];

    const int bz = blockIdx.z;
    A += (long)bz * strideA;
    B += (long)bz * strideB;
    C += (long)bz * strideC;

    const int m0 = blockIdx.y * BM;
    const int n0 = blockIdx.x * BN;
    const int tid = threadIdx.x;
    const int ty = tid / 16;        // 0..15
    const int tx = tid % 16;        // 0..15

    // A/B(NT) tile loader indices: 128 rows x 16 cols, float4 along K
    const int lrow = tid / 4;       // 0..63
    const int lcol = (tid % 4) * 4; // 0,4,8,12
    // B(NN) tile loader indices: 16 rows x 128 cols, float4 along N
    const int brow = tid / 32;      // 0..7
    const int bcol = (tid % 32) * 4;

    float acc[8][8];
    #pragma unroll
    for (int i = 0; i < 8; i++)
        #pragma unroll
        for (int j = 0; j < 8; j++) acc[i][j] = 0.f;

    for (int k0 = 0; k0 < K; k0 += BK) {
        // --- load A tile (transpose into As[k][m]) ---
        #pragma unroll
        for (int p = 0; p < 2; p++) {
            const int r = lrow + p * 64;
            float4 v = *(const float4*)(A + (long)(m0 + r) * K + k0 + lcol);
            As[lcol + 0][r] = v.x;
            As[lcol + 1][r] = v.y;
            As[lcol + 2][r] = v.z;
            As[lcol + 3][r] = v.w;
        }
        // --- load B tile ---
        if (TRANS_B) {
            #pragma unroll
            for (int p = 0; p < 2; p++) {
                const int r = lrow + p * 64;
                float4 v = *(const float4*)(B + (long)(n0 + r) * K + k0 + lcol);
                Bs[lcol + 0][r] = v.x;
                Bs[lcol + 1][r] = v.y;
                Bs[lcol + 2][r] = v.z;
                Bs[lcol + 3][r] = v.w;
            }
        } else {
            #pragma unroll
            for (int p = 0; p < 2; p++) {
                const int r = brow + p * 8;
                float4 v = *(const float4*)(B + (long)(k0 + r) * N + n0 + bcol);
                *(float4*)&Bs[r][bcol] = v;
            }
        }
        __syncthreads();

        // --- compute ---
        #pragma unroll
        for (int kk = 0; kk < BK; kk++) {
            float a[8], b[8];
            #pragma unroll
            for (int i = 0; i < 8; i++) a[i] = As[kk][ty * 8 + i];
            #pragma unroll
            for (int j = 0; j < 8; j++) b[j] = Bs[kk][tx * 8 + j];
            #pragma unroll
            for (int i = 0; i < 8; i++)
                #pragma unroll
                for (int j = 0; j < 8; j++)
                    acc[i][j] += a[i] * b[j];
        }
        __syncthreads();
    }

    // --- epilogue ---
    #pragma unroll
    for (int i = 0; i < 8; i++) {
        const long m = m0 + ty * 8 + i;
        #pragma unroll
        for (int j = 0; j < 8; j++) {
            const int n = n0 + tx * 8 + j;
            float v = acc[i][j] * alpha;
            if (HAS_BIAS) v += bias[n];
            C[m * N + n] = v;
        }
    }
}

// ---------------------------------------------------------------------------
// Row softmax: one 256-thread block per row of length SEQ (2048).
// Row values held in registers (8 per thread).
// ---------------------------------------------------------------------------
__global__ __launch_bounds__(256)
void softmax_rows(float* __restrict__ P)
{
    float* p = P + (long)blockIdx.x * SEQ;
    const int tid = threadIdx.x;
    __shared__ float red[8];

    float v[8];
    #pragma unroll
    for (int i = 0; i < 8; i++) v[i] = p[tid + i * 256];

    // max
    float m = v[0];
    #pragma unroll
    for (int i = 1; i < 8; i++) m = fmaxf(m, v[i]);
    #pragma unroll
    for (int o = 16; o; o >>= 1) m = fmaxf(m, __shfl_xor_sync(0xffffffffu, m, o));
    if ((tid & 31) == 0) red[tid >> 5] = m;
    __syncthreads();
    m = red[0];
    #pragma unroll
    for (int w = 1; w < 8; w++) m = fmaxf(m, red[w]);
    __syncthreads();

    // exp + sum
    float s = 0.f;
    #pragma unroll
    for (int i = 0; i < 8; i++) { v[i] = __expf(v[i] - m); s += v[i]; }
    #pragma unroll
    for (int o = 16; o; o >>= 1) s += __shfl_xor_sync(0xffffffffu, s, o);
    if ((tid & 31) == 0) red[tid >> 5] = s;
    __syncthreads();
    s = 0.f;
    #pragma unroll
    for (int w = 0; w < 8; w++) s += red[w];
    const float inv = 1.f / s;

    #pragma unroll
    for (int i = 0; i < 8; i++) p[tid + i * 256] = v[i] * inv;
}

// ---------------------------------------------------------------------------
// Launch
// ---------------------------------------------------------------------------
extern "C" void kernel_launch(void* const* d_in, const int* in_sizes, int n_in,
                              void* d_out, int out_size)
{
    const float* x  = (const float*)d_in[0];
    const float* Wq = (const float*)d_in[1];
    const float* bq = (const float*)d_in[2];
    const float* Wk = (const float*)d_in[3];
    const float* bk = (const float*)d_in[4];
    const float* Wv = (const float*)d_in[5];
    const float* bv = (const float*)d_in[6];
    float* out = (float*)d_out;

    float *Q, *K, *V, *P;
    cudaGetSymbolAddress((void**)&Q, g_Q);
    cudaGetSymbolAddress((void**)&K, g_K);
    cudaGetSymbolAddress((void**)&V, g_V);
    cudaGetSymbolAddress((void**)&P, g_P);

    const dim3 blk(256);
    const int MQ = BATCH * SEQ;          // 8192
    const long sQKV = (long)SEQ * DIM;   // per-batch Q/K/V stride
    const long sP   = (long)SEQ * SEQ;   // per-batch scores stride

    // QKV projections: [8192,1024] = x[8192,1024] * W^T[1024,1024] + b
    {
        dim3 grid(DIM / BN, MQ / BM, 1);
        gemm_kernel<true,  true><<<grid, blk>>>(x, Wq, bq, Q, MQ, DIM, DIM, 0, 0, 0, 1.f);
        gemm_kernel<true,  true><<<grid, blk>>>(x, Wk, bk, K, MQ, DIM, DIM, 0, 0, 0, 1.f);
        gemm_kernel<true,  true><<<grid, blk>>>(x, Wv, bv, V, MQ, DIM, DIM, 0, 0, 0, 1.f);
    }

    // scores: per batch  P = (1/sqrt(1024)) * Q * K^T   [2048,2048]
    {
        dim3 grid(SEQ / BN, SEQ / BM, BATCH);
        gemm_kernel<true, false><<<grid, blk>>>(Q, K, nullptr, P,
                                                SEQ, SEQ, DIM, sQKV, sQKV, sP, 0.03125f);
    }

    // softmax over last axis
    softmax_rows<<<BATCH * SEQ, blk>>>(P);

    // out: per batch  O = P * V   [2048,1024]  (NN)
    {
        dim3 grid(DIM / BN, SEQ / BM, BATCH);
        gemm_kernel<false, false><<<grid, blk>>>(P, V, nullptr, out,
                                                 SEQ, DIM, SEQ, sP, sQKV, sQKV, 1.f);
    }
}

// round 3
// speedup vs baseline: 2.0797x; 2.0797x over previous
#include <cuda_runtime.h>
#include <cuda_bf16.h>
#include <cstdint>

#define BATCH 4
#define SEQ   2048
#define DIM   1024
#define MQ    (BATCH * SEQ)   // 8192

typedef __nv_bfloat16 bf16;

// ---------------------------------------------------------------------------
// Persistent scratch (device globals — allocation-free per harness rules)
// ---------------------------------------------------------------------------
__device__ bf16  g_xhi[(long)MQ * DIM],  g_xlo[(long)MQ * DIM];
__device__ bf16  g_Whi[3][(long)DIM * DIM], g_Wlo[3][(long)DIM * DIM];
__device__ bf16  g_Qhi[(long)MQ * DIM],  g_Qlo[(long)MQ * DIM];
__device__ bf16  g_Khi[(long)MQ * DIM],  g_Klo[(long)MQ * DIM];
__device__ bf16  g_Vhi[(long)MQ * DIM],  g_Vlo[(long)MQ * DIM];
__device__ float g_S[(long)BATCH * SEQ * SEQ];
__device__ bf16  g_Phi[(long)BATCH * SEQ * SEQ], g_Plo[(long)BATCH * SEQ * SEQ];

// ---------------------------------------------------------------------------
// helpers
// ---------------------------------------------------------------------------
__device__ __forceinline__ uint32_t smem_u32(const void* p) {
    uint32_t a;
    asm("{ .reg .u64 t; cvta.to.shared.u64 t, %1; cvt.u32.u64 %0, t; }" : "=r"(a) : "l"(p));
    return a;
}
__device__ __forceinline__ void ldsm4(uint32_t r[4], uint32_t addr) {
    asm volatile("ldmatrix.sync.aligned.m8n8.x4.shared.b16 {%0,%1,%2,%3}, [%4];"
                 : "=r"(r[0]), "=r"(r[1]), "=r"(r[2]), "=r"(r[3]) : "r"(addr));
}
__device__ __forceinline__ void ldsm4t(uint32_t r[4], uint32_t addr) {
    asm volatile("ldmatrix.sync.aligned.m8n8.x4.trans.shared.b16 {%0,%1,%2,%3}, [%4];"
                 : "=r"(r[0]), "=r"(r[1]), "=r"(r[2]), "=r"(r[3]) : "r"(addr));
}
__device__ __forceinline__ void mma16816(float c[4], const uint32_t a[4],
                                         uint32_t b0, uint32_t b1) {
    asm volatile(
        "mma.sync.aligned.m16n8k16.row.col.f32.bf16.bf16.f32 "
        "{%0,%1,%2,%3}, {%4,%5,%6,%7}, {%8,%9}, {%0,%1,%2,%3};"
        : "+f"(c[0]), "+f"(c[1]), "+f"(c[2]), "+f"(c[3])
        : "r"(a[0]), "r"(a[1]), "r"(a[2]), "r"(a[3]), "r"(b0), "r"(b1));
}
__device__ __forceinline__ void store_hilo(bf16* Chi, bf16* Clo, long off,
                                           float v0, float v1) {
    bf16 h0 = __float2bfloat16(v0), h1 = __float2bfloat16(v1);
    __nv_bfloat162 hh; hh.x = h0; hh.y = h1;
    *(__nv_bfloat162*)(Chi + off) = hh;
    __nv_bfloat162 ll;
    ll.x = __float2bfloat16(v0 - __bfloat162float(h0));
    ll.y = __float2bfloat16(v1 - __bfloat162float(h1));
    *(__nv_bfloat162*)(Clo + off) = ll;
}

// ---------------------------------------------------------------------------
// fp32 -> bf16 hi/lo split
// ---------------------------------------------------------------------------
__global__ void split_f32(const float* __restrict__ s, bf16* __restrict__ hi,
                          bf16* __restrict__ lo, int n4)
{
    int i = blockIdx.x * blockDim.x + threadIdx.x;
    if (i >= n4) return;
    float4 v = ((const float4*)s)[i];
    float f[4] = {v.x, v.y, v.z, v.w};
    #pragma unroll
    for (int j = 0; j < 4; j++) {
        bf16 h = __float2bfloat16(f[j]);
        hi[4 * i + j] = h;
        lo[4 * i + j] = __float2bfloat16(f[j] - __bfloat162float(h));
    }
}

// ---------------------------------------------------------------------------
// Split-bf16 HMMA GEMM: C[M,N] = A[M,K] * op(B)
//   BKMAJOR=1: B is [N,K] row-major (NT).   BKMAJOR=0: B is [K,N] row-major (NN).
//   MODE 0: bf16 hi/lo out + bias.          MODE 2: fp32 out * alpha.
// CTA tile 128x128, BK=32, 8 warps (2x4), warp tile 64x32.
// ---------------------------------------------------------------------------
#define LDA   40    // bf16 row stride for 32-wide K-major tiles
#define LDBNN 136   // bf16 row stride for 128-wide NN B tiles

template <bool BKMAJOR, int MODE>
__global__ __launch_bounds__(256)
void hmma_gemm(const bf16* __restrict__ Ahi, const bf16* __restrict__ Alo,
               const bf16* __restrict__ Bhi, const bf16* __restrict__ Blo,
               const float* __restrict__ bias,
               float* __restrict__ Cf, bf16* __restrict__ Chi, bf16* __restrict__ Clo,
               int M, int N, int K, long sA, long sB, long sC, float alpha)
{
    constexpr int BELEMS = BKMAJOR ? 128 * LDA : 32 * LDBNN;
    __shared__ bf16 sAhi[128 * LDA], sAlo[128 * LDA];
    __shared__ bf16 sBhi[BELEMS],    sBlo[BELEMS];

    const int tid = threadIdx.x;
    const int lane = tid & 31;
    const int wid = tid >> 5;
    const int wm = wid >> 2;        // 0..1
    const int wn = wid & 3;         // 0..3

    const int bz = blockIdx.z;
    Ahi += bz * sA;  Alo += bz * sA;
    Bhi += bz * sB;  Blo += bz * sB;
    const int m0 = blockIdx.y * 128;
    const int n0 = blockIdx.x * 128;

    // loader indices
    const int ar0 = tid >> 2,  ac0 = (tid & 3) * 8;           // A/B-NT: idx = tid
    const int ar1 = (tid + 256) >> 2, ac1 = ((tid + 256) & 3) * 8;
    const int br0 = tid >> 4,  bc0 = (tid & 15) * 8;          // B-NN
    const int br1 = (tid + 256) >> 4, bc1 = ((tid + 256) & 15) * 8;

    float c[4][4][4];
    #pragma unroll
    for (int i = 0; i < 4; i++)
        #pragma unroll
        for (int j = 0; j < 4; j++)
            #pragma unroll
            for (int r = 0; r < 4; r++) c[i][j][r] = 0.f;

    uint4 pah[2], pal[2], pbh[2], pbl[2];

    // prefetch first slab
    {
        pah[0] = *(const uint4*)(Ahi + (long)(m0 + ar0) * K + ac0);
        pah[1] = *(const uint4*)(Ahi + (long)(m0 + ar1) * K + ac1);
        pal[0] = *(const uint4*)(Alo + (long)(m0 + ar0) * K + ac0);
        pal[1] = *(const uint4*)(Alo + (long)(m0 + ar1) * K + ac1);
        if (BKMAJOR) {
            pbh[0] = *(const uint4*)(Bhi + (long)(n0 + ar0) * K + ac0);
            pbh[1] = *(const uint4*)(Bhi + (long)(n0 + ar1) * K + ac1);
            pbl[0] = *(const uint4*)(Blo + (long)(n0 + ar0) * K + ac0);
            pbl[1] = *(const uint4*)(Blo + (long)(n0 + ar1) * K + ac1);
        } else {
            pbh[0] = *(const uint4*)(Bhi + (long)br0 * N + n0 + bc0);
            pbh[1] = *(const uint4*)(Bhi + (long)br1 * N + n0 + bc1);
            pbl[0] = *(const uint4*)(Blo + (long)br0 * N + n0 + bc0);
            pbl[1] = *(const uint4*)(Blo + (long)br1 * N + n0 + bc1);
        }
    }

    for (int k0 = 0; k0 < K; k0 += 32) {
        // store staged slab to smem
        *(uint4*)&sAhi[ar0 * LDA + ac0] = pah[0];
        *(uint4*)&sAhi[ar1 * LDA + ac1] = pah[1];
        *(uint4*)&sAlo[ar0 * LDA + ac0] = pal[0];
        *(uint4*)&sAlo[ar1 * LDA + ac1] = pal[1];
        if (BKMAJOR) {
            *(uint4*)&sBhi[ar0 * LDA + ac0] = pbh[0];
            *(uint4*)&sBhi[ar1 * LDA + ac1] = pbh[1];
            *(uint4*)&sBlo[ar0 * LDA + ac0] = pbl[0];
            *(uint4*)&sBlo[ar1 * LDA + ac1] = pbl[1];
        } else {
            *(uint4*)&sBhi[br0 * LDBNN + bc0] = pbh[0];
            *(uint4*)&sBhi[br1 * LDBNN + bc1] = pbh[1];
            *(uint4*)&sBlo[br0 * LDBNN + bc0] = pbl[0];
            *(uint4*)&sBlo[br1 * LDBNN + bc1] = pbl[1];
        }
        __syncthreads();

        // prefetch next slab (in flight during compute)
        const int kn = k0 + 32;
        if (kn < K) {
            pah[0] = *(const uint4*)(Ahi + (long)(m0 + ar0) * K + kn + ac0);
            pah[1] = *(const uint4*)(Ahi + (long)(m0 + ar1) * K + kn + ac1);
            pal[0] = *(const uint4*)(Alo + (long)(m0 + ar0) * K + kn + ac0);
            pal[1] = *(const uint4*)(Alo + (long)(m0 + ar1) * K + kn + ac1);
            if (BKMAJOR) {
                pbh[0] = *(const uint4*)(Bhi + (long)(n0 + ar0) * K + kn + ac0);
                pbh[1] = *(const uint4*)(Bhi + (long)(n0 + ar1) * K + kn + ac1);
                pbl[0] = *(const uint4*)(Blo + (long)(n0 + ar0) * K + kn + ac0);
                pbl[1] = *(const uint4*)(Blo + (long)(n0 + ar1) * K + kn + ac1);
            } else {
                pbh[0] = *(const uint4*)(Bhi + (long)(kn + br0) * N + n0 + bc0);
                pbh[1] = *(const uint4*)(Bhi + (long)(kn + br1) * N + n0 + bc1);
                pbl[0] = *(const uint4*)(Blo + (long)(kn + br0) * N + n0 + bc0);
                pbl[1] = *(const uint4*)(Blo + (long)(kn + br1) * N + n0 + bc1);
            }
        }

        // compute: 2 k-steps of 16
        #pragma unroll
        for (int ks = 0; ks < 2; ks++) {
            const int kk = ks * 16;
            uint32_t fah[4][4], fal[4][4], fbh[2][4], fbl[2][4];
            #pragma unroll
            for (int mf = 0; mf < 4; mf++) {
                const int row = wm * 64 + mf * 16 + (lane & 15);
                const int col = kk + (lane >> 4) * 8;
                ldsm4(fah[mf], smem_u32(&sAhi[row * LDA + col]));
                ldsm4(fal[mf], smem_u32(&sAlo[row * LDA + col]));
            }
            if (BKMAJOR) {
                #pragma unroll
                for (int q = 0; q < 2; q++) {
                    const int row = wn * 32 + q * 16 + (lane & 15);
                    const int col = kk + (lane >> 4) * 8;
                    ldsm4(fbh[q], smem_u32(&sBhi[row * LDA + col]));
                    ldsm4(fbl[q], smem_u32(&sBlo[row * LDA + col]));
                }
            } else {
                #pragma unroll
                for (int q = 0; q < 2; q++) {
                    const int row = kk + (lane >> 4) * 8 + (lane & 7);
                    const int col = wn * 32 + q * 16 + ((lane >> 3) & 1) * 8;
                    ldsm4t(fbh[q], smem_u32(&sBhi[row * LDBNN + col]));
                    ldsm4t(fbl[q], smem_u32(&sBlo[row * LDBNN + col]));
                }
            }
            #pragma unroll
            for (int mf = 0; mf < 4; mf++)
                #pragma unroll
                for (int nf = 0; nf < 4; nf++) {
                    const int q = nf >> 1, g = nf & 1;
                    mma16816(c[mf][nf], fah[mf], fbh[q][g], fbh[q][g + 2]);
                    mma16816(c[mf][nf], fah[mf], fbl[q][g], fbl[q][g + 2]);
                    mma16816(c[mf][nf], fal[mf], fbh[q][g], fbh[q][g + 2]);
                }
        }
        __syncthreads();
    }

    // ---- epilogue ----
    #pragma unroll
    for (int mf = 0; mf < 4; mf++) {
        const int m_lo = m0 + wm * 64 + mf * 16 + (lane >> 2);
        #pragma unroll
        for (int nf = 0; nf < 4; nf++) {
            const int n = n0 + wn * 32 + nf * 8 + (lane & 3) * 2;
            if (MODE == 0) {
                const float b0 = bias[n], b1 = bias[n + 1];
                store_hilo(Chi, Clo, (long)m_lo * N + n,
                           c[mf][nf][0] + b0, c[mf][nf][1] + b1);
                store_hilo(Chi, Clo, (long)(m_lo + 8) * N + n,
                           c[mf][nf][2] + b0, c[mf][nf][3] + b1);
            } else {
                float* co = Cf + bz * sC;
                float2 v0 = make_float2(c[mf][nf][0] * alpha, c[mf][nf][1] * alpha);
                float2 v1 = make_float2(c[mf][nf][2] * alpha, c[mf][nf][3] * alpha);
                *(float2*)(co + (long)m_lo * N + n) = v0;
                *(float2*)(co + (long)(m_lo + 8) * N + n) = v1;
            }
        }
    }
}

// ---------------------------------------------------------------------------
// Softmax over rows of g_S (len SEQ) -> bf16 hi/lo probs
// ---------------------------------------------------------------------------
__global__ __launch_bounds__(256)
void softmax_rows(const float* __restrict__ S, bf16* __restrict__ Phi, bf16* __restrict__ Plo)
{
    const float* p = S + (long)blockIdx.x * SEQ;
    bf16* ph = Phi + (long)blockIdx.x * SEQ;
    bf16* pl = Plo + (long)blockIdx.x * SEQ;
    const int tid = threadIdx.x;
    __shared__ float red[8];

    float v[8];
    #pragma unroll
    for (int i = 0; i < 8; i++) v[i] = p[tid + i * 256];

    float m = v[0];
    #pragma unroll
    for (int i = 1; i < 8; i++) m = fmaxf(m, v[i]);
    #pragma unroll
    for (int o = 16; o; o >>= 1) m = fmaxf(m, __shfl_xor_sync(0xffffffffu, m, o));
    if ((tid & 31) == 0) red[tid >> 5] = m;
    __syncthreads();
    m = red[0];
    #pragma unroll
    for (int w = 1; w < 8; w++) m = fmaxf(m, red[w]);
    __syncthreads();

    float s = 0.f;
    #pragma unroll
    for (int i = 0; i < 8; i++) { v[i] = __expf(v[i] - m); s += v[i]; }
    #pragma unroll
    for (int o = 16; o; o >>= 1) s += __shfl_xor_sync(0xffffffffu, s, o);
    if ((tid & 31) == 0) red[tid >> 5] = s;
    __syncthreads();
    s = 0.f;
    #pragma unroll
    for (int w = 0; w < 8; w++) s += red[w];
    const float inv = 1.f / s;

    #pragma unroll
    for (int i = 0; i < 8; i++) {
        const float q = v[i] * inv;
        bf16 h = __float2bfloat16(q);
        ph[tid + i * 256] = h;
        pl[tid + i * 256] = __float2bfloat16(q - __bfloat162float(h));
    }
}

// ---------------------------------------------------------------------------
// Launch
// ---------------------------------------------------------------------------
extern "C" void kernel_launch(void* const* d_in, const int* in_sizes, int n_in,
                              void* d_out, int out_size)
{
    const float* x  = (const float*)d_in[0];
    const float* Wq = (const float*)d_in[1];
    const float* bq = (const float*)d_in[2];
    const float* Wk = (const float*)d_in[3];
    const float* bk = (const float*)d_in[4];
    const float* Wv = (const float*)d_in[5];
    const float* bv = (const float*)d_in[6];
    float* out = (float*)d_out;

    bf16 *xhi, *xlo, *Whi, *Wlo, *Qhi, *Qlo, *Khi, *Klo, *Vhi, *Vlo, *Phi, *Plo;
    float* S;
    cudaGetSymbolAddress((void**)&xhi, g_xhi);   cudaGetSymbolAddress((void**)&xlo, g_xlo);
    cudaGetSymbolAddress((void**)&Whi, g_Whi);   cudaGetSymbolAddress((void**)&Wlo, g_Wlo);
    cudaGetSymbolAddress((void**)&Qhi, g_Qhi);   cudaGetSymbolAddress((void**)&Qlo, g_Qlo);
    cudaGetSymbolAddress((void**)&Khi, g_Khi);   cudaGetSymbolAddress((void**)&Klo, g_Klo);
    cudaGetSymbolAddress((void**)&Vhi, g_Vhi);   cudaGetSymbolAddress((void**)&Vlo, g_Vlo);
    cudaGetSymbolAddress((void**)&S, g_S);
    cudaGetSymbolAddress((void**)&Phi, g_Phi);   cudaGetSymbolAddress((void**)&Plo, g_Plo);

    const long WSZ = (long)DIM * DIM;

    // 1) split fp32 -> bf16 hi/lo
    split_f32<<<(MQ * DIM / 4 + 255) / 256, 256>>>(x, xhi, xlo, MQ * DIM / 4);
    split_f32<<<(WSZ / 4 + 255) / 256, 256>>>(Wq, Whi + 0 * WSZ, Wlo + 0 * WSZ, WSZ / 4);
    split_f32<<<(WSZ / 4 + 255) / 256, 256>>>(Wk, Whi + 1 * WSZ, Wlo + 1 * WSZ, WSZ / 4);
    split_f32<<<(WSZ / 4 + 255) / 256, 256>>>(Wv, Whi + 2 * WSZ, Wlo + 2 * WSZ, WSZ / 4);

    // 2) projections: [8192,1024] = x * W^T + b   (NT, bf16 hi/lo out)
    {
        dim3 grid(DIM / 128, MQ / 128, 1), blk(256);
        hmma_gemm<true, 0><<<grid, blk>>>(xhi, xlo, Whi + 0 * WSZ, Wlo + 0 * WSZ, bq,
                                          nullptr, Qhi, Qlo, MQ, DIM, DIM, 0, 0, 0, 1.f);
        hmma_gemm<true, 0><<<grid, blk>>>(xhi, xlo, Whi + 1 * WSZ, Wlo + 1 * WSZ, bk,
                                          nullptr, Khi, Klo, MQ, DIM, DIM, 0, 0, 0, 1.f);
        hmma_gemm<true, 0><<<grid, blk>>>(xhi, xlo, Whi + 2 * WSZ, Wlo + 2 * WSZ, bv,
                                          nullptr, Vhi, Vlo, MQ, DIM, DIM, 0, 0, 0, 1.f);
    }

    // 3) scores: S = (1/32) Q K^T  per batch  (NT, fp32 out)
    {
        dim3 grid(SEQ / 128, SEQ / 128, BATCH), blk(256);
        hmma_gemm<true, 2><<<grid, blk>>>(Qhi, Qlo, Khi, Klo, nullptr,
                                          S, nullptr, nullptr, SEQ, SEQ, DIM,
                                          (long)SEQ * DIM, (long)SEQ * DIM, (long)SEQ * SEQ,
                                          0.03125f);
    }

    // 4) softmax -> P hi/lo
    softmax_rows<<<BATCH * SEQ, 256>>>(S, Phi, Plo);

    // 5) out = P @ V  per batch  (NN via ldmatrix.trans, fp32 out)
    {
        dim3 grid(DIM / 128, SEQ / 128, BATCH), blk(256);
        hmma_gemm<false, 2><<<grid, blk>>>(Phi, Plo, Vhi, Vlo, nullptr,
                                           out, nullptr, nullptr, SEQ, DIM, SEQ,
                                           (long)SEQ * SEQ, (long)SEQ * DIM, (long)SEQ * DIM,
                                           1.f);
    }
}